// round 8
// baseline (speedup 1.0000x reference)
#include <cuda_runtime.h>
#include <float.h>

// Problem constants
#define NB     8
#define NC1    2048
#define HW     56
#define PLANE  (HW*HW)          // 3136
#define SR     60               // smem row stride (floats)
#define SPLANE (58*SR)          // 3480 floats per padded plane
#define NPLANES 16
#define SMEM_BYTES (NPLANES*SPLANE*4)   // 222720 B
#define OC_PER_BLK 128
#define NTASKS (OC_PER_BLK*14)  // 1792
#define NTHREADS 256            // 1792/256 = 7 tasks/thread, exactly even

typedef unsigned long long ull;

#define PACK2(p, lo, hi) \
    asm("mov.b64 %0, {%1, %2};" : "=l"(p) : "f"(lo), "f"(hi))
#define UNPACK2(lo, hi, p) \
    asm("mov.b64 {%0, %1}, %2;" : "=f"(lo), "=f"(hi) : "l"(p))
#define FMA2(d, a, b, c) \
    asm("fma.rn.f32x2 %0, %1, %2, %3;" : "=l"(d) : "l"(a), "l"(b), "l"(c))

// 0 = index stored as int32 (JAX default, x64 disabled), 1 = genuine int64
__device__ int g_idx_is_i64;

__global__ void detect_index_dtype(const unsigned int* __restrict__ idx_words) {
    // int64 layout: odd words (high halves) of first 32 entries are all 0.
    // int32 layout: those words are index[1],[3],...,[63] of a permutation of
    // [0,8192): at most one of them is zero.
    if (threadIdx.x == 0) {
        int any_nonzero = 0;
        for (int k = 0; k < 32; k++) any_nonzero |= (idx_words[2*k + 1] != 0u);
        g_idx_is_i64 = !any_nonzero;
    }
}

__global__ __launch_bounds__(NTHREADS)
void fused_conv_gather_max(const float* __restrict__ x,
                           const float* __restrict__ Wt,
                           const float* __restrict__ b1,
                           const int* __restrict__ index32,
                           float* __restrict__ out) {
    extern __shared__ float sm[];   // 16 padded planes of 58 x 60
    const int ocg = blockIdx.x;     // oc group (0..15)
    const int n   = blockIdx.y;
    const int tid = threadIdx.x;
    const int is64 = g_idx_is_i64;

    // ---- Stage all 16 input planes once (aligned STS.128 via shuffle) ----
    // Padded: plane[r+1][c+1] = x[r][c]; float4 group hl of a padded row is
    // {in[4hl-1], in[4hl], in[4hl+1], in[4hl+2]}.
    const int grp = tid >> 4;       // 0..15 (16-lane groups)
    const int hl  = tid & 15;
#pragma unroll 1
    for (int g = 0; g < NPLANES; g++) {
        const float* src = x + (long)(n*NPLANES + g)*PLANE;
        float* pb = sm + g*SPLANE;
#pragma unroll 1
        for (int r = grp; r < HW; r += 16) {
            float4 v = make_float4(0.f, 0.f, 0.f, 0.f);
            if (hl < 14) v = ((const float4*)(src + r*HW))[hl];
            float pw = __shfl_up_sync(0xffffffffu, v.w, 1, 16);
            float4 o = make_float4(hl ? pw : 0.f, v.x, v.y, v.z);
            if (hl < 15) ((float4*)(pb + (r+1)*SR))[hl] = o;   // aligned STS.128
        }
    }
    // Zero padded bottom row 57 of each plane (row 0 is never read: the
    // partial-sum init below accounts for it). 16 planes x 15 float4.
    if (tid < NPLANES*15) {
        int g = tid / 15, q = tid - g*15;
        ((float4*)(sm + g*SPLANE + 57*SR))[q] = make_float4(0.f, 0.f, 0.f, 0.f);
    }
    __syncthreads();

    // ---- Tasks: (oc_local, sx) columns; thread scans all rows once -------
#pragma unroll 1
    for (int p = 0; p < 7; p++) {
        const int t   = p*NTHREADS + tid;
        const int ocl = t / 14;
        const int sx  = t - ocl*14;
        const int oc  = ocg*OC_PER_BLK + ocl;

        // Resolve 4 source channels; pack weights/bias as (k,k) f32x2 pairs
        ull kp[4][9], bp[4];
        const float* rp[4];
#pragma unroll
        for (int g = 0; g < 4; g++) {
            int iv;
            if (is64) iv = (int)((const long long*)index32)[oc*4 + g];
            else      iv = index32[oc*4 + g];
            int c  = iv & (NC1 - 1);
            int ic = c >> 7;                 // 128 out-channels per input chan
            rp[g] = sm + ic*SPLANE + sx*4 + SR;   // padded row 1
            const float* wp = Wt + c*9;
#pragma unroll
            for (int j = 0; j < 9; j++) { float kk = __ldg(wp + j); PACK2(kp[g][j], kk, kk); }
            float bb = __ldg(b1 + c);
            PACK2(bp[g], bb, bb);
        }

        // Packed partial-row accumulators per channel:
        //  P1* = bias + top-taps of the next output row
        //  P0* = P1 + mid-taps (completed by bot-taps of current scan row)
        // a = outputs (0,1), b = outputs (2,3)
        ull P0a[4], P0b[4], P1a[4], P1b[4];
#pragma unroll
        for (int g = 0; g < 4; g++) {
            P0a[g] = bp[g]; P0b[g] = bp[g]; P1a[g] = bp[g]; P1b[g] = bp[g];
        }

        float* outp = out + ((long)(n*NC1 + oc))*PLANE + sx*4;

        // Peeled first scan row (rr=1): advances partials, no store.
#pragma unroll
        for (int g = 0; g < 4; g++) {
            float4 A = *(const float4*)rp[g];
            float2 Bq = *(const float2*)(rp[g] + 4);
            rp[g] += SR;
            ull A01, A12, A23, A34, A45;
            PACK2(A01, A.x, A.y); PACK2(A12, A.y, A.z); PACK2(A23, A.z, A.w);
            PACK2(A34, A.w, Bq.x); PACK2(A45, Bq.x, Bq.y);
            ull u;
            u = P1a[g]; FMA2(u, kp[g][3], A01, u); FMA2(u, kp[g][4], A12, u); FMA2(u, kp[g][5], A23, u); P0a[g] = u;
            u = P1b[g]; FMA2(u, kp[g][3], A23, u); FMA2(u, kp[g][4], A34, u); FMA2(u, kp[g][5], A45, u); P0b[g] = u;
            u = bp[g];  FMA2(u, kp[g][0], A01, u); FMA2(u, kp[g][1], A12, u); FMA2(u, kp[g][2], A23, u); P1a[g] = u;
            u = bp[g];  FMA2(u, kp[g][0], A23, u); FMA2(u, kp[g][1], A34, u); FMA2(u, kp[g][2], A45, u); P1b[g] = u;
        }

#pragma unroll 1
        for (int rr = 2; rr <= 57; rr++) {
            float m0, m1, m2, m3;
#pragma unroll
            for (int g = 0; g < 4; g++) {
                float4 A = *(const float4*)rp[g];
                float2 Bq = *(const float2*)(rp[g] + 4);
                rp[g] += SR;
                ull A01, A12, A23, A34, A45;
                PACK2(A01, A.x, A.y); PACK2(A12, A.y, A.z); PACK2(A23, A.z, A.w);
                PACK2(A34, A.w, Bq.x); PACK2(A45, Bq.x, Bq.y);

                // Complete output row rr-2 with bottom taps
                ull Ca = P0a[g], Cb = P0b[g];
                FMA2(Ca, kp[g][6], A01, Ca); FMA2(Ca, kp[g][7], A12, Ca); FMA2(Ca, kp[g][8], A23, Ca);
                FMA2(Cb, kp[g][6], A23, Cb); FMA2(Cb, kp[g][7], A34, Cb); FMA2(Cb, kp[g][8], A45, Cb);

                ull u;
                u = P1a[g]; FMA2(u, kp[g][3], A01, u); FMA2(u, kp[g][4], A12, u); FMA2(u, kp[g][5], A23, u); P0a[g] = u;
                u = P1b[g]; FMA2(u, kp[g][3], A23, u); FMA2(u, kp[g][4], A34, u); FMA2(u, kp[g][5], A45, u); P0b[g] = u;
                u = bp[g];  FMA2(u, kp[g][0], A01, u); FMA2(u, kp[g][1], A12, u); FMA2(u, kp[g][2], A23, u); P1a[g] = u;
                u = bp[g];  FMA2(u, kp[g][0], A23, u); FMA2(u, kp[g][1], A34, u); FMA2(u, kp[g][2], A45, u); P1b[g] = u;

                float c0, c1, c2, c3;
                UNPACK2(c0, c1, Ca); UNPACK2(c2, c3, Cb);
                if (g == 0) { m0 = c0; m1 = c1; m2 = c2; m3 = c3; }
                else {
                    m0 = fmaxf(m0, c0); m1 = fmaxf(m1, c1);
                    m2 = fmaxf(m2, c2); m3 = fmaxf(m3, c3);
                }
            }
            *(float4*)outp = make_float4(m0, m1, m2, m3);
            outp += HW;
        }
    }
}

extern "C" void kernel_launch(void* const* d_in, const int* in_sizes, int n_in,
                              void* d_out, int out_size) {
    const float* x     = (const float*)d_in[0];
    const float* Wt    = (const float*)d_in[1];
    const float* b1    = (const float*)d_in[2];
    const int*   index = (const int*)d_in[3];
    float*       out   = (float*)d_out;

    cudaFuncSetAttribute(fused_conv_gather_max,
                         cudaFuncAttributeMaxDynamicSharedMemorySize, SMEM_BYTES);

    detect_index_dtype<<<1, 32>>>((const unsigned int*)index);

    dim3 grid(NC1/OC_PER_BLK, NB);   // 16 x 8 = 128 blocks
    fused_conv_gather_max<<<grid, NTHREADS, SMEM_BYTES>>>(x, Wt, b1, index, out);
}

// round 9
// speedup vs baseline: 1.3675x; 1.3675x over previous
#include <cuda_runtime.h>
#include <float.h>

// Problem constants
#define NB     8
#define NC1    2048
#define HW     56
#define PLANE  (HW*HW)          // 3136
#define SR     60               // smem row stride (floats)
#define SPLANE (58*SR)          // 3480 floats per padded plane
#define NPLANES 16
#define SMEM_BYTES (NPLANES*SPLANE*4)   // 222720 B
#define OC_PER_BLK 128
#define NTHREADS 512
// Tasks: (oc_local, sx, half-rows). 128*14*2 = 3584 = 512 * 7 exactly.
#define NTASKS 3584

// 0 = index stored as int32 (JAX default, x64 disabled), 1 = genuine int64
__device__ int g_idx_is_i64;

__global__ void detect_index_dtype(const unsigned int* __restrict__ idx_words) {
    // int64 layout: odd words (high halves) of first 32 entries are all 0.
    // int32 layout: those words are index[1],[3],...,[63] of a permutation of
    // [0,8192): at most one of them is zero.
    if (threadIdx.x == 0) {
        int any_nonzero = 0;
        for (int k = 0; k < 32; k++) any_nonzero |= (idx_words[2*k + 1] != 0u);
        g_idx_is_i64 = !any_nonzero;
    }
}

__global__ __launch_bounds__(NTHREADS)
void fused_conv_gather_max(const float* __restrict__ x,
                           const float* __restrict__ Wt,
                           const float* __restrict__ b1,
                           const int* __restrict__ index32,
                           float* __restrict__ out) {
    extern __shared__ float sm[];   // 16 padded planes of 58 x 60
    const int ocg = blockIdx.x;     // oc group (0..15)
    const int n   = blockIdx.y;
    const int tid = threadIdx.x;
    const int is64 = g_idx_is_i64;

    // ---- Stage all 16 input planes once (aligned STS.128 via shuffle) ----
    // Padded: plane[r+1][c+1] = x[r][c]; float4 group hl of a padded row is
    // {in[4hl-1], in[4hl], in[4hl+1], in[4hl+2]}.
    const int grp = tid >> 4;       // 0..31 (16-lane groups)
    const int hl  = tid & 15;
#pragma unroll 1
    for (int g = 0; g < NPLANES; g++) {
        const float* src = x + (long)(n*NPLANES + g)*PLANE;
        float* pb = sm + g*SPLANE;
#pragma unroll 1
        for (int r = grp; r < HW; r += 32) {
            float4 v = make_float4(0.f, 0.f, 0.f, 0.f);
            if (hl < 14) v = ((const float4*)(src + r*HW))[hl];
            float pw = __shfl_up_sync(0xffffffffu, v.w, 1, 16);
            float4 o = make_float4(hl ? pw : 0.f, v.x, v.y, v.z);
            if (hl < 15) ((float4*)(pb + (r+1)*SR))[hl] = o;   // aligned STS.128
        }
    }
    // Zero padded bottom row 57 of each plane (row 0 is never read: the
    // partial-sum init below accounts for it). 16 planes x 15 float4.
    if (tid < NPLANES*15) {
        int g = tid / 15, q = tid - g*15;
        ((float4*)(sm + g*SPLANE + 57*SR))[q] = make_float4(0.f, 0.f, 0.f, 0.f);
    }
    __syncthreads();

    // ---- Tasks: 7 per thread, each = (ocl, sx, half) covering 28 output rows
#pragma unroll 1
    for (int p = 0; p < 7; p++) {
        const int t    = p*NTHREADS + tid;
        const int ocl  = t / 28;
        const int rem  = t - ocl*28;
        const int sx   = rem >> 1;
        const int half = rem & 1;
        const int oc   = ocg*OC_PER_BLK + ocl;

        // Resolve 4 source channels; load weights/bias
        float k[4][9], bs[4];
        const float* rp[4];
#pragma unroll
        for (int g = 0; g < 4; g++) {
            int iv;
            if (is64) iv = (int)((const long long*)index32)[oc*4 + g];
            else      iv = index32[oc*4 + g];
            int c  = iv & (NC1 - 1);
            int ic = c >> 7;                 // 128 out-channels per input chan
            // First padded row this task touches: 1 for half 0, 28 for half 1
            rp[g] = sm + ic*SPLANE + sx*4 + (half ? 28*SR : SR);
            const float* wp = Wt + c*9;
#pragma unroll
            for (int j = 0; j < 9; j++) k[g][j] = __ldg(wp + j);
            bs[g] = __ldg(b1 + c);
        }

        // Partial-row accumulators per channel:
        //  p1[g][j] = bias + top-taps of the next output row
        //  p0[g][j] = p1 + mid-taps (completed by bot-taps of current scan row)
        float p0[4][4], p1[4][4];

        // Peel A (half 1 only): p1 = bias + top-taps of padded row 28
        if (half) {
#pragma unroll
            for (int g = 0; g < 4; g++) {
                float4 a = *(const float4*)rp[g];
                float2 bq = *(const float2*)(rp[g] + 4);
                rp[g] += SR;
                float v0=a.x, v1=a.y, v2=a.z, v3=a.w, v4=bq.x, v5=bq.y;
#pragma unroll
                for (int j = 0; j < 4; j++) {
                    float w0 = (j==0)?v0:(j==1)?v1:(j==2)?v2:v3;
                    float w1 = (j==0)?v1:(j==1)?v2:(j==2)?v3:v4;
                    float w2 = (j==0)?v2:(j==1)?v3:(j==2)?v4:v5;
                    p1[g][j] = fmaf(k[g][2], w2, fmaf(k[g][1], w1, fmaf(k[g][0], w0, bs[g])));
                }
            }
        } else {
#pragma unroll
            for (int g = 0; g < 4; g++)
#pragma unroll
                for (int j = 0; j < 4; j++) p1[g][j] = bs[g];  // zero top row
        }

        // Peel B: p0 = p1 + mid-taps; p1 = bias + top-taps (padded row 1 or 29)
#pragma unroll
        for (int g = 0; g < 4; g++) {
            float4 a = *(const float4*)rp[g];
            float2 bq = *(const float2*)(rp[g] + 4);
            rp[g] += SR;
            float v0=a.x, v1=a.y, v2=a.z, v3=a.w, v4=bq.x, v5=bq.y;
#pragma unroll
            for (int j = 0; j < 4; j++) {
                float w0 = (j==0)?v0:(j==1)?v1:(j==2)?v2:v3;
                float w1 = (j==0)?v1:(j==1)?v2:(j==2)?v3:v4;
                float w2 = (j==0)?v2:(j==1)?v3:(j==2)?v4:v5;
                p0[g][j] = fmaf(k[g][5], w2, fmaf(k[g][4], w1, fmaf(k[g][3], w0, p1[g][j])));
                p1[g][j] = fmaf(k[g][2], w2, fmaf(k[g][1], w1, fmaf(k[g][0], w0, bs[g])));
            }
        }

        float* outp = out + ((long)(n*NC1 + oc))*PLANE + (half*28)*HW + sx*4;

        // 28 output rows; scan rows (padded) rs+2 .. rs+29
#pragma unroll 2
        for (int rr = 0; rr < 28; rr++) {
            float m0, m1, m2, m3;
#pragma unroll
            for (int g = 0; g < 4; g++) {
                float4 a = *(const float4*)rp[g];
                float2 bq = *(const float2*)(rp[g] + 4);
                rp[g] += SR;
                float v0=a.x, v1=a.y, v2=a.z, v3=a.w, v4=bq.x, v5=bq.y;
                const float k0=k[g][0], k1=k[g][1], k2=k[g][2];
                const float k3=k[g][3], k4=k[g][4], k5=k[g][5];
                const float k6=k[g][6], k7=k[g][7], k8=k[g][8];
                const float bb = bs[g];
                float c0, c1, c2, c3;
#pragma unroll
                for (int j = 0; j < 4; j++) {
                    float w0 = (j==0)?v0:(j==1)?v1:(j==2)?v2:v3;
                    float w1 = (j==0)?v1:(j==1)?v2:(j==2)?v3:v4;
                    float w2 = (j==0)?v2:(j==1)?v3:(j==2)?v4:v5;
                    float cc = fmaf(k8, w2, fmaf(k7, w1, fmaf(k6, w0, p0[g][j])));
                    if (j==0) c0=cc; else if (j==1) c1=cc; else if (j==2) c2=cc; else c3=cc;
                    p0[g][j] = fmaf(k5, w2, fmaf(k4, w1, fmaf(k3, w0, p1[g][j])));
                    p1[g][j] = fmaf(k2, w2, fmaf(k1, w1, fmaf(k0, w0, bb)));
                }
                if (g == 0) { m0 = c0; m1 = c1; m2 = c2; m3 = c3; }
                else {
                    m0 = fmaxf(m0, c0); m1 = fmaxf(m1, c1);
                    m2 = fmaxf(m2, c2); m3 = fmaxf(m3, c3);
                }
            }
            *(float4*)outp = make_float4(m0, m1, m2, m3);
            outp += HW;
        }
    }
}

extern "C" void kernel_launch(void* const* d_in, const int* in_sizes, int n_in,
                              void* d_out, int out_size) {
    const float* x     = (const float*)d_in[0];
    const float* Wt    = (const float*)d_in[1];
    const float* b1    = (const float*)d_in[2];
    const int*   index = (const int*)d_in[3];
    float*       out   = (float*)d_out;

    cudaFuncSetAttribute(fused_conv_gather_max,
                         cudaFuncAttributeMaxDynamicSharedMemorySize, SMEM_BYTES);

    detect_index_dtype<<<1, 32>>>((const unsigned int*)index);

    dim3 grid(NC1/OC_PER_BLK, NB);   // 16 x 8 = 128 blocks
    fused_conv_gather_max<<<grid, NTHREADS, SMEM_BYTES>>>(x, Wt, b1, index, out);
}